// round 11
// baseline (speedup 1.0000x reference)
#include <cuda_runtime.h>

// Problem constants (fixed by the reference: B=8, S=2048, D=1024)
#define BB 8
#define SS 2048
#define DD 1024
#define CHUNKS 64
#define ROWS_PER_CHUNK (SS / CHUNKS)   // 32
#define TOTAL_CTAS (CHUNKS * BB)        // 512 colsum CTAs (all co-resident)
#define GEMV_CTAS 128                   // CTAs that continue into reduce+gemv

// Scratch (written, never accumulated -> no zero-init needed).
__device__ float g_partial[BB * CHUNKS * DD];   // 2 MB
__device__ float g_xsum[BB * DD];               // 32 KB
__device__ int   g_cnt;    // colsum-publish counter   (self-resetting)
__device__ int   g_cnt2;   // xsum-publish counter     (self-resetting)
__device__ int   g_done;   // exit counter for reset handshake

// ---------------------------------------------------------------------------
// Single fused kernel. grid = 512 CTAs, block = 256.
// Co-residency: 55 regs * 256 thr = ~14K regs (<=4 CTAs/SM by regfile),
// 37 KB smem (<=6 CTAs/SM) -> 148 SMs hold >= 592 CTAs >= 512. All CTAs are
// resident from launch, so the spin barriers below cannot deadlock.
//
// Phase 1 (all 512): colsum chunk (b = cta/64, c = cta%64) — bit-identical to
//   the measured-good R7 colsum. Publish via fence + g_cnt.
// Phase 2 (CTAs 0..127): spin g_cnt==512, reduce 16 float4 columns of xsum
//   (fixed blockIdx-based slice, fixed fold order -> deterministic).
// Phase 3 (CTAs 0..127): spin g_cnt2==128, then the measured-good gemv.
// Reset: g_done round; last CTA zeroes all counters (graph-replay-safe).
// ---------------------------------------------------------------------------
__global__ __launch_bounds__(256) void fused_kernel(const float* __restrict__ x,
                                                    const float* __restrict__ Wv,
                                                    const float* __restrict__ bv,
                                                    float* __restrict__ out) {
    __shared__ float  xs[BB * DD];      // 32 KB (phase 3)
    __shared__ float4 red[16][16];      // 4 KB  (phase 2)

    const int t   = threadIdx.x;
    const int cta = blockIdx.x;         // 0..511

    // ==== Phase 1: colsum chunk ========================================
    {
        const int b = cta >> 6;         // batch 0..7
        const int c = cta & 63;         // chunk 0..63

        const float4* __restrict__ xp =
            reinterpret_cast<const float4*>(x + ((size_t)b * SS + (size_t)c * ROWS_PER_CHUNK) * DD) + t;

        float4 a0 = make_float4(0.f, 0.f, 0.f, 0.f);
        float4 a1 = make_float4(0.f, 0.f, 0.f, 0.f);
        float4 a2 = make_float4(0.f, 0.f, 0.f, 0.f);
        float4 a3 = make_float4(0.f, 0.f, 0.f, 0.f);

        #pragma unroll
        for (int s = 0; s < ROWS_PER_CHUNK; s += 8) {
            float4 v0 = xp[(size_t)(s + 0) * (DD / 4)];
            float4 v1 = xp[(size_t)(s + 1) * (DD / 4)];
            float4 v2 = xp[(size_t)(s + 2) * (DD / 4)];
            float4 v3 = xp[(size_t)(s + 3) * (DD / 4)];
            float4 v4 = xp[(size_t)(s + 4) * (DD / 4)];
            float4 v5 = xp[(size_t)(s + 5) * (DD / 4)];
            float4 v6 = xp[(size_t)(s + 6) * (DD / 4)];
            float4 v7 = xp[(size_t)(s + 7) * (DD / 4)];
            a0.x += v0.x; a0.y += v0.y; a0.z += v0.z; a0.w += v0.w;
            a1.x += v1.x; a1.y += v1.y; a1.z += v1.z; a1.w += v1.w;
            a2.x += v2.x; a2.y += v2.y; a2.z += v2.z; a2.w += v2.w;
            a3.x += v3.x; a3.y += v3.y; a3.z += v3.z; a3.w += v3.w;
            a0.x += v4.x; a0.y += v4.y; a0.z += v4.z; a0.w += v4.w;
            a1.x += v5.x; a1.y += v5.y; a1.z += v5.z; a1.w += v5.w;
            a2.x += v6.x; a2.y += v6.y; a2.z += v6.z; a2.w += v6.w;
            a3.x += v7.x; a3.y += v7.y; a3.z += v7.z; a3.w += v7.w;
        }

        float4 acc;
        acc.x = (a0.x + a1.x) + (a2.x + a3.x);
        acc.y = (a0.y + a1.y) + (a2.y + a3.y);
        acc.z = (a0.z + a1.z) + (a2.z + a3.z);
        acc.w = (a0.w + a1.w) + (a2.w + a3.w);

        reinterpret_cast<float4*>(g_partial + ((size_t)b * CHUNKS + c) * DD)[t] = acc;
    }

    // Publish: partial writes globally visible before the count.
    __syncthreads();
    __threadfence();
    if (t == 0) atomicAdd(&g_cnt, 1);

    if (cta >= GEMV_CTAS) return;       // 384 CTAs are done

    // ==== Barrier 1: wait for all 512 colsum publishes =================
    if (t == 0) {
        while (*((volatile int*)&g_cnt) < TOTAL_CTAS) { }
    }
    __syncthreads();

    // ==== Phase 2: reduce this CTA's 16 float4 columns of xsum =========
    {
        const int tx = t & 15;                  // col within slice
        const int tg = t >> 4;                  // chunk group 0..15
        const int gc4  = cta * 16 + tx;         // global float4 col [0,2048)
        const int b    = gc4 >> 8;              // batch
        const int col4 = gc4 & 255;

        const float4* __restrict__ pp =
            reinterpret_cast<const float4*>(g_partial) + (size_t)b * CHUNKS * (DD / 4) + col4;

        float4 v0 = pp[(size_t)(tg * 4 + 0) * (DD / 4)];
        float4 v1 = pp[(size_t)(tg * 4 + 1) * (DD / 4)];
        float4 v2 = pp[(size_t)(tg * 4 + 2) * (DD / 4)];
        float4 v3 = pp[(size_t)(tg * 4 + 3) * (DD / 4)];
        float4 a;
        a.x = (v0.x + v1.x) + (v2.x + v3.x);
        a.y = (v0.y + v1.y) + (v2.y + v3.y);
        a.z = (v0.z + v1.z) + (v2.z + v3.z);
        a.w = (v0.w + v1.w) + (v2.w + v3.w);
        red[tg][tx] = a;
        __syncthreads();

        if (tg == 0) {
            float4 s = make_float4(0.f, 0.f, 0.f, 0.f);
            #pragma unroll
            for (int g = 0; g < 16; ++g) {      // fixed order -> deterministic
                float4 r = red[g][tx];
                s.x += r.x; s.y += r.y; s.z += r.z; s.w += r.w;
            }
            reinterpret_cast<float4*>(g_xsum)[gc4] = s;
        }
    }

    __syncthreads();
    __threadfence();
    if (t == 0) atomicAdd(&g_cnt2, 1);

    // ==== Barrier 2: wait for all 128 xsum publishes ===================
    if (t == 0) {
        while (*((volatile int*)&g_cnt2) < GEMV_CTAS) { }
    }
    __syncthreads();

    // ==== Phase 3: gemv (measured-good path, unchanged) ================
    {
        const float4* __restrict__ src = reinterpret_cast<const float4*>(g_xsum);
        float4*       __restrict__ dst = reinterpret_cast<float4*>(xs);
        #pragma unroll
        for (int i = 0; i < (BB * DD / 4) / 256; ++i)   // 8 iterations
            dst[t + 256 * i] = src[t + 256 * i];
    }
    __syncthreads();

    const int warp = t >> 5;
    const int lane = t & 31;
    const int e = cta * 8 + warp;

    const float4* __restrict__ wrow = reinterpret_cast<const float4*>(Wv + (size_t)e * DD);

    float s0 = 0.f, s1 = 0.f, s2 = 0.f, s3 = 0.f;
    float s4 = 0.f, s5 = 0.f, s6 = 0.f, s7 = 0.f;

    #pragma unroll
    for (int i = 0; i < 8; ++i) {
        const int c4 = lane + 32 * i;
        float4 w = wrow[c4];
        #define ACC(bi, s) { \
            float4 xv = reinterpret_cast<const float4*>(xs + (bi) * DD)[c4]; \
            s += w.x * xv.x + w.y * xv.y + w.z * xv.z + w.w * xv.w; }
        ACC(0, s0) ACC(1, s1) ACC(2, s2) ACC(3, s3)
        ACC(4, s4) ACC(5, s5) ACC(6, s6) ACC(7, s7)
        #undef ACC
    }

    #pragma unroll
    for (int off = 16; off; off >>= 1) {
        s0 += __shfl_xor_sync(0xffffffffu, s0, off);
        s1 += __shfl_xor_sync(0xffffffffu, s1, off);
        s2 += __shfl_xor_sync(0xffffffffu, s2, off);
        s3 += __shfl_xor_sync(0xffffffffu, s3, off);
        s4 += __shfl_xor_sync(0xffffffffu, s4, off);
        s5 += __shfl_xor_sync(0xffffffffu, s5, off);
        s6 += __shfl_xor_sync(0xffffffffu, s6, off);
        s7 += __shfl_xor_sync(0xffffffffu, s7, off);
    }

    if (lane == 0) {
        const float bias = (float)SS * bv[e];
        out[0 * DD + e] = s0 + bias;
        out[1 * DD + e] = s1 + bias;
        out[2 * DD + e] = s2 + bias;
        out[3 * DD + e] = s3 + bias;
        out[4 * DD + e] = s4 + bias;
        out[5 * DD + e] = s5 + bias;
        out[6 * DD + e] = s6 + bias;
        out[7 * DD + e] = s7 + bias;
    }

    // ==== Counter reset for graph replay (after both spins passed) =====
    __syncthreads();
    if (t == 0) {
        int o = atomicAdd(&g_done, 1);
        if (o == GEMV_CTAS - 1) {
            atomicExch(&g_cnt, 0);
            atomicExch(&g_cnt2, 0);
            atomicExch(&g_done, 0);
        }
    }
}

// ---------------------------------------------------------------------------
// kernel_launch — graph-capturable, allocation-free, deterministic.
// Input order (metadata): 0=x, 1=Wq, 2=bq, 3=Wk, 4=bk, 5=Wv, 6=bv
// ---------------------------------------------------------------------------
extern "C" void kernel_launch(void* const* d_in, const int* in_sizes, int n_in,
                              void* d_out, int out_size) {
    (void)in_sizes; (void)n_in; (void)out_size;
    const float* x  = (const float*)d_in[0];
    const float* Wv = (const float*)d_in[5];
    const float* bv = (const float*)d_in[6];
    float* out = (float*)d_out;

    fused_kernel<<<TOTAL_CTAS, 256>>>(x, Wv, bv, out);
}

// round 12
// speedup vs baseline: 1.1284x; 1.1284x over previous
#include <cuda_runtime.h>

// Problem constants (fixed by the reference: B=8, S=2048, D=1024)
#define BB 8
#define SS 2048
#define DD 1024
#define CHUNKS 64
#define ROWS_PER_CHUNK (SS / CHUNKS)   // 32
#define GEMV_CTAS 128                   // <= #SMs -> all co-resident (spin-safe)

// Scratch (written, never accumulated -> no zero-init needed).
__device__ float g_partial[BB * CHUNKS * DD];   // 2 MB
__device__ float g_xsum[BB * DD];               // 32 KB
__device__ int   g_cnt;                         // reduce-publish counter (self-resetting)
__device__ int   g_done;                        // exit counter for reset handshake

// ---------------------------------------------------------------------------
// Kernel A: per-(batch, chunk) column sum of x over S.  [R7 structure]
// grid = (64, 8) = 512 CTAs, block = 256; thread t owns float4 column t.
// x is read exactly once -> __ldcs (evict-first streaming) so the 67 MB
// stream does not thrash L1/L2 (partials + Wv benefit from staying cached).
// ---------------------------------------------------------------------------
__global__ __launch_bounds__(256) void colsum_kernel(const float* __restrict__ x) {
    const int c = blockIdx.x;
    const int b = blockIdx.y;
    const int t = threadIdx.x;

    const float4* __restrict__ xp =
        reinterpret_cast<const float4*>(x + ((size_t)b * SS + (size_t)c * ROWS_PER_CHUNK) * DD) + t;

    float4 a0 = make_float4(0.f, 0.f, 0.f, 0.f);
    float4 a1 = make_float4(0.f, 0.f, 0.f, 0.f);
    float4 a2 = make_float4(0.f, 0.f, 0.f, 0.f);
    float4 a3 = make_float4(0.f, 0.f, 0.f, 0.f);

    #pragma unroll
    for (int s = 0; s < ROWS_PER_CHUNK; s += 8) {
        float4 v0 = __ldcs(xp + (size_t)(s + 0) * (DD / 4));
        float4 v1 = __ldcs(xp + (size_t)(s + 1) * (DD / 4));
        float4 v2 = __ldcs(xp + (size_t)(s + 2) * (DD / 4));
        float4 v3 = __ldcs(xp + (size_t)(s + 3) * (DD / 4));
        float4 v4 = __ldcs(xp + (size_t)(s + 4) * (DD / 4));
        float4 v5 = __ldcs(xp + (size_t)(s + 5) * (DD / 4));
        float4 v6 = __ldcs(xp + (size_t)(s + 6) * (DD / 4));
        float4 v7 = __ldcs(xp + (size_t)(s + 7) * (DD / 4));
        a0.x += v0.x; a0.y += v0.y; a0.z += v0.z; a0.w += v0.w;
        a1.x += v1.x; a1.y += v1.y; a1.z += v1.z; a1.w += v1.w;
        a2.x += v2.x; a2.y += v2.y; a2.z += v2.z; a2.w += v2.w;
        a3.x += v3.x; a3.y += v3.y; a3.z += v3.z; a3.w += v3.w;
        a0.x += v4.x; a0.y += v4.y; a0.z += v4.z; a0.w += v4.w;
        a1.x += v5.x; a1.y += v5.y; a1.z += v5.z; a1.w += v5.w;
        a2.x += v6.x; a2.y += v6.y; a2.z += v6.z; a2.w += v6.w;
        a3.x += v7.x; a3.y += v7.y; a3.z += v7.z; a3.w += v7.w;
    }

    float4 acc;
    acc.x = (a0.x + a1.x) + (a2.x + a3.x);
    acc.y = (a0.y + a1.y) + (a2.y + a3.y);
    acc.z = (a0.z + a1.z) + (a2.z + a3.z);
    acc.w = (a0.w + a1.w) + (a2.w + a3.w);

    reinterpret_cast<float4*>(g_partial + ((size_t)b * CHUNKS + c) * DD)[t] = acc;
}

// ---------------------------------------------------------------------------
// Kernel B (fused reduce + gemv): grid = 128 CTAs, block = 256.  [R10 exact]
// Phase 1: CTA k reduces xsum float4 slice [k*16, k*16+16) over all 64 chunks
//          (fixed fold order -> deterministic), writes g_xsum, fences, counts.
// Sync:    all 128 CTAs co-resident (grid <= SM count) -> spin on g_cnt.
// Phase 2: measured-good gemv — stage all 8 xsum vectors to smem, warp owns
//          Wv row e, dots against all 8 batches.
// Reset:   g_done second round; last CTA zeroes both counters (replay-safe).
// ---------------------------------------------------------------------------
__global__ __launch_bounds__(256) void gemv_fused_kernel(const float* __restrict__ Wv,
                                                         const float* __restrict__ bv,
                                                         float* __restrict__ out) {
    __shared__ float  xs[BB * DD];      // 32 KB
    __shared__ float4 red[16][16];      // 4 KB

    const int t   = threadIdx.x;
    const int cta = blockIdx.x;         // 0..127

    // ---- Phase 1: reduce this CTA's 16 float4 columns of xsum ----------
    {
        const int tx = t & 15;                  // col within slice
        const int tg = t >> 4;                  // chunk group 0..15
        const int gc4  = cta * 16 + tx;         // global float4 col in [0,2048)
        const int b    = gc4 >> 8;              // batch (256 float4 per batch)
        const int col4 = gc4 & 255;

        const float4* __restrict__ pp =
            reinterpret_cast<const float4*>(g_partial) + (size_t)b * CHUNKS * (DD / 4) + col4;

        float4 v0 = pp[(size_t)(tg * 4 + 0) * (DD / 4)];
        float4 v1 = pp[(size_t)(tg * 4 + 1) * (DD / 4)];
        float4 v2 = pp[(size_t)(tg * 4 + 2) * (DD / 4)];
        float4 v3 = pp[(size_t)(tg * 4 + 3) * (DD / 4)];
        float4 a;
        a.x = (v0.x + v1.x) + (v2.x + v3.x);
        a.y = (v0.y + v1.y) + (v2.y + v3.y);
        a.z = (v0.z + v1.z) + (v2.z + v3.z);
        a.w = (v0.w + v1.w) + (v2.w + v3.w);
        red[tg][tx] = a;
        __syncthreads();

        if (tg == 0) {
            float4 s = make_float4(0.f, 0.f, 0.f, 0.f);
            #pragma unroll
            for (int g = 0; g < 16; ++g) {      // fixed order -> deterministic
                float4 r = red[g][tx];
                s.x += r.x; s.y += r.y; s.z += r.z; s.w += r.w;
            }
            reinterpret_cast<float4*>(g_xsum)[gc4] = s;
        }
    }

    // Publish: writes above must be globally visible before the count.
    __syncthreads();
    __threadfence();
    if (t == 0) atomicAdd(&g_cnt, 1);

    // ---- Grid-wide spin sync (all CTAs resident -> cannot deadlock) ----
    if (t == 0) {
        while (*((volatile int*)&g_cnt) < GEMV_CTAS) { }
    }
    __syncthreads();

    // ---- Phase 2: gemv (unchanged measured-good path) ------------------
    {
        const float4* __restrict__ src = reinterpret_cast<const float4*>(g_xsum);
        float4*       __restrict__ dst = reinterpret_cast<float4*>(xs);
        #pragma unroll
        for (int i = 0; i < (BB * DD / 4) / 256; ++i)   // 8 iterations
            dst[t + 256 * i] = src[t + 256 * i];
    }
    __syncthreads();

    const int warp = t >> 5;
    const int lane = t & 31;
    const int e = cta * 8 + warp;

    const float4* __restrict__ wrow = reinterpret_cast<const float4*>(Wv + (size_t)e * DD);

    float s0 = 0.f, s1 = 0.f, s2 = 0.f, s3 = 0.f;
    float s4 = 0.f, s5 = 0.f, s6 = 0.f, s7 = 0.f;

    #pragma unroll
    for (int i = 0; i < 8; ++i) {
        const int c4 = lane + 32 * i;
        float4 w = wrow[c4];
        #define ACC(bi, s) { \
            float4 xv = reinterpret_cast<const float4*>(xs + (bi) * DD)[c4]; \
            s += w.x * xv.x + w.y * xv.y + w.z * xv.z + w.w * xv.w; }
        ACC(0, s0) ACC(1, s1) ACC(2, s2) ACC(3, s3)
        ACC(4, s4) ACC(5, s5) ACC(6, s6) ACC(7, s7)
        #undef ACC
    }

    #pragma unroll
    for (int off = 16; off; off >>= 1) {
        s0 += __shfl_xor_sync(0xffffffffu, s0, off);
        s1 += __shfl_xor_sync(0xffffffffu, s1, off);
        s2 += __shfl_xor_sync(0xffffffffu, s2, off);
        s3 += __shfl_xor_sync(0xffffffffu, s3, off);
        s4 += __shfl_xor_sync(0xffffffffu, s4, off);
        s5 += __shfl_xor_sync(0xffffffffu, s5, off);
        s6 += __shfl_xor_sync(0xffffffffu, s6, off);
        s7 += __shfl_xor_sync(0xffffffffu, s7, off);
    }

    if (lane == 0) {
        const float bias = (float)SS * bv[e];
        out[0 * DD + e] = s0 + bias;
        out[1 * DD + e] = s1 + bias;
        out[2 * DD + e] = s2 + bias;
        out[3 * DD + e] = s3 + bias;
        out[4 * DD + e] = s4 + bias;
        out[5 * DD + e] = s5 + bias;
        out[6 * DD + e] = s6 + bias;
        out[7 * DD + e] = s7 + bias;
    }

    // ---- Counter reset for graph replay (after all CTAs passed spin) ---
    __syncthreads();
    if (t == 0) {
        int o = atomicAdd(&g_done, 1);
        if (o == GEMV_CTAS - 1) {
            atomicExch(&g_cnt, 0);
            atomicExch(&g_done, 0);
        }
    }
}

// ---------------------------------------------------------------------------
// kernel_launch — graph-capturable, allocation-free, deterministic.
// Input order (metadata): 0=x, 1=Wq, 2=bq, 3=Wk, 4=bk, 5=Wv, 6=bv
// ---------------------------------------------------------------------------
extern "C" void kernel_launch(void* const* d_in, const int* in_sizes, int n_in,
                              void* d_out, int out_size) {
    (void)in_sizes; (void)n_in; (void)out_size;
    const float* x  = (const float*)d_in[0];
    const float* Wv = (const float*)d_in[5];
    const float* bv = (const float*)d_in[6];
    float* out = (float*)d_out;

    colsum_kernel<<<dim3(CHUNKS, BB), 256>>>(x);
    gemv_fused_kernel<<<GEMV_CTAS, 256>>>(Wv, bv, out);
}

// round 14
// speedup vs baseline: 1.1911x; 1.0556x over previous
#include <cuda_runtime.h>

// Problem constants (fixed by the reference: B=8, S=2048, D=1024)
#define BB 8
#define SS 2048
#define DD 1024
#define CHUNKS 64
#define ROWS_PER_CHUNK (SS / CHUNKS)   // 32
#define GEMV_CTAS 128                   // <= #SMs -> all co-resident (spin-safe)

// Scratch (written, never accumulated -> no zero-init needed).
__device__ float g_partial[BB * CHUNKS * DD];   // 2 MB
__device__ float g_xsum[BB * DD];               // 32 KB
__device__ int   g_cnt;                         // reduce-publish counter (self-resetting)
__device__ int   g_done;                        // exit counter for reset handshake

// ---------------------------------------------------------------------------
// Kernel A: per-(batch, chunk) column sum of x over S.  [R10 exact]
// grid = (64, 8) = 512 CTAs (all co-resident), block = 256.
// ---------------------------------------------------------------------------
__global__ __launch_bounds__(256) void colsum_kernel(const float* __restrict__ x) {
    const int c = blockIdx.x;
    const int b = blockIdx.y;
    const int t = threadIdx.x;

    const float4* __restrict__ xp =
        reinterpret_cast<const float4*>(x + ((size_t)b * SS + (size_t)c * ROWS_PER_CHUNK) * DD) + t;

    float4 a0 = make_float4(0.f, 0.f, 0.f, 0.f);
    float4 a1 = make_float4(0.f, 0.f, 0.f, 0.f);
    float4 a2 = make_float4(0.f, 0.f, 0.f, 0.f);
    float4 a3 = make_float4(0.f, 0.f, 0.f, 0.f);

    #pragma unroll
    for (int s = 0; s < ROWS_PER_CHUNK; s += 8) {
        float4 v0 = xp[(size_t)(s + 0) * (DD / 4)];
        float4 v1 = xp[(size_t)(s + 1) * (DD / 4)];
        float4 v2 = xp[(size_t)(s + 2) * (DD / 4)];
        float4 v3 = xp[(size_t)(s + 3) * (DD / 4)];
        float4 v4 = xp[(size_t)(s + 4) * (DD / 4)];
        float4 v5 = xp[(size_t)(s + 5) * (DD / 4)];
        float4 v6 = xp[(size_t)(s + 6) * (DD / 4)];
        float4 v7 = xp[(size_t)(s + 7) * (DD / 4)];
        a0.x += v0.x; a0.y += v0.y; a0.z += v0.z; a0.w += v0.w;
        a1.x += v1.x; a1.y += v1.y; a1.z += v1.z; a1.w += v1.w;
        a2.x += v2.x; a2.y += v2.y; a2.z += v2.z; a2.w += v2.w;
        a3.x += v3.x; a3.y += v3.y; a3.z += v3.z; a3.w += v3.w;
        a0.x += v4.x; a0.y += v4.y; a0.z += v4.z; a0.w += v4.w;
        a1.x += v5.x; a1.y += v5.y; a1.z += v5.z; a1.w += v5.w;
        a2.x += v6.x; a2.y += v6.y; a2.z += v6.z; a2.w += v6.w;
        a3.x += v7.x; a3.y += v7.y; a3.z += v7.z; a3.w += v7.w;
    }

    float4 acc;
    acc.x = (a0.x + a1.x) + (a2.x + a3.x);
    acc.y = (a0.y + a1.y) + (a2.y + a3.y);
    acc.z = (a0.z + a1.z) + (a2.z + a3.z);
    acc.w = (a0.w + a1.w) + (a2.w + a3.w);

    reinterpret_cast<float4*>(g_partial + ((size_t)b * CHUNKS + c) * DD)[t] = acc;
}

// Accumulate one float4 column across all 8 batches (fixed order).
__device__ __forceinline__ void acc_col(const float* __restrict__ xs, int c4,
                                        const float4& w,
                                        float& s0, float& s1, float& s2, float& s3,
                                        float& s4, float& s5, float& s6, float& s7) {
    const float4* __restrict__ xsv = reinterpret_cast<const float4*>(xs);
    float4 x0 = xsv[0 * (DD / 4) + c4];
    float4 x1 = xsv[1 * (DD / 4) + c4];
    float4 x2 = xsv[2 * (DD / 4) + c4];
    float4 x3 = xsv[3 * (DD / 4) + c4];
    float4 x4 = xsv[4 * (DD / 4) + c4];
    float4 x5 = xsv[5 * (DD / 4) + c4];
    float4 x6 = xsv[6 * (DD / 4) + c4];
    float4 x7 = xsv[7 * (DD / 4) + c4];
    s0 += w.x * x0.x + w.y * x0.y + w.z * x0.z + w.w * x0.w;
    s1 += w.x * x1.x + w.y * x1.y + w.z * x1.z + w.w * x1.w;
    s2 += w.x * x2.x + w.y * x2.y + w.z * x2.z + w.w * x2.w;
    s3 += w.x * x3.x + w.y * x3.y + w.z * x3.z + w.w * x3.w;
    s4 += w.x * x4.x + w.y * x4.y + w.z * x4.z + w.w * x4.w;
    s5 += w.x * x5.x + w.y * x5.y + w.z * x5.z + w.w * x5.w;
    s6 += w.x * x6.x + w.y * x6.y + w.z * x6.z + w.w * x6.w;
    s7 += w.x * x7.x + w.y * x7.y + w.z * x7.z + w.w * x7.w;
}

// ---------------------------------------------------------------------------
// Kernel B (fused reduce + gemv): grid = 128 CTAs, block = 256.
// Wv row + bv are loaded into registers BEFORE the reduce/spin — independent
// of colsum output, so their latency hides behind phase 1 + the grid sync.
// Phase 1: CTA k reduces xsum float4 slice [k*16, k*16+16) over all 64 chunks
//          (fixed fold order -> deterministic), writes g_xsum, fences, counts.
// Sync:    all 128 CTAs co-resident (grid <= SM count) -> spin on g_cnt.
// Phase 2: stage all 8 xsum vectors to smem; warp owns Wv row e, dots against
//          all 8 batches using the preloaded Wv registers.
// Reset:   g_done second round; last CTA zeroes both counters (replay-safe).
// ---------------------------------------------------------------------------
__global__ __launch_bounds__(256) void gemv_fused_kernel(const float* __restrict__ Wv,
                                                         const float* __restrict__ bv,
                                                         float* __restrict__ out) {
    __shared__ float  xs[BB * DD];      // 32 KB
    __shared__ float4 red[16][16];      // 4 KB

    const int t   = threadIdx.x;
    const int cta = blockIdx.x;         // 0..127
    const int warp = t >> 5;
    const int lane = t & 31;
    const int e = cta * 8 + warp;       // output feature owned by this warp

    // ---- Prefetch (independent of colsum): Wv row + bias ---------------
    const float4* __restrict__ wrow = reinterpret_cast<const float4*>(Wv + (size_t)e * DD);
    float4 w0 = wrow[lane +   0];
    float4 w1 = wrow[lane +  32];
    float4 w2 = wrow[lane +  64];
    float4 w3 = wrow[lane +  96];
    float4 w4 = wrow[lane + 128];
    float4 w5 = wrow[lane + 160];
    float4 w6 = wrow[lane + 192];
    float4 w7 = wrow[lane + 224];
    const float bias = (float)SS * bv[e];

    // ---- Phase 1: reduce this CTA's 16 float4 columns of xsum ----------
    {
        const int tx = t & 15;                  // col within slice
        const int tg = t >> 4;                  // chunk group 0..15
        const int gc4  = cta * 16 + tx;         // global float4 col in [0,2048)
        const int b    = gc4 >> 8;              // batch (256 float4 per batch)
        const int col4 = gc4 & 255;

        const float4* __restrict__ pp =
            reinterpret_cast<const float4*>(g_partial) + (size_t)b * CHUNKS * (DD / 4) + col4;

        float4 v0 = pp[(size_t)(tg * 4 + 0) * (DD / 4)];
        float4 v1 = pp[(size_t)(tg * 4 + 1) * (DD / 4)];
        float4 v2 = pp[(size_t)(tg * 4 + 2) * (DD / 4)];
        float4 v3 = pp[(size_t)(tg * 4 + 3) * (DD / 4)];
        float4 a;
        a.x = (v0.x + v1.x) + (v2.x + v3.x);
        a.y = (v0.y + v1.y) + (v2.y + v3.y);
        a.z = (v0.z + v1.z) + (v2.z + v3.z);
        a.w = (v0.w + v1.w) + (v2.w + v3.w);
        red[tg][tx] = a;
        __syncthreads();

        if (tg == 0) {
            float4 s = make_float4(0.f, 0.f, 0.f, 0.f);
            #pragma unroll
            for (int g = 0; g < 16; ++g) {      // fixed order -> deterministic
                float4 r = red[g][tx];
                s.x += r.x; s.y += r.y; s.z += r.z; s.w += r.w;
            }
            reinterpret_cast<float4*>(g_xsum)[gc4] = s;
        }
    }

    // Publish: writes above must be globally visible before the count.
    __syncthreads();
    __threadfence();
    if (t == 0) atomicAdd(&g_cnt, 1);

    // ---- Grid-wide spin sync (all CTAs resident -> cannot deadlock) ----
    if (t == 0) {
        while (*((volatile int*)&g_cnt) < GEMV_CTAS) { }
    }
    __syncthreads();

    // ---- Phase 2: gemv using preloaded Wv registers --------------------
    {
        const float4* __restrict__ src = reinterpret_cast<const float4*>(g_xsum);
        float4*       __restrict__ dst = reinterpret_cast<float4*>(xs);
        #pragma unroll
        for (int i = 0; i < (BB * DD / 4) / 256; ++i)   // 8 iterations
            dst[t + 256 * i] = src[t + 256 * i];
    }
    __syncthreads();

    float s0 = 0.f, s1 = 0.f, s2 = 0.f, s3 = 0.f;
    float s4 = 0.f, s5 = 0.f, s6 = 0.f, s7 = 0.f;

    acc_col(xs, lane +   0, w0, s0, s1, s2, s3, s4, s5, s6, s7);
    acc_col(xs, lane +  32, w1, s0, s1, s2, s3, s4, s5, s6, s7);
    acc_col(xs, lane +  64, w2, s0, s1, s2, s3, s4, s5, s6, s7);
    acc_col(xs, lane +  96, w3, s0, s1, s2, s3, s4, s5, s6, s7);
    acc_col(xs, lane + 128, w4, s0, s1, s2, s3, s4, s5, s6, s7);
    acc_col(xs, lane + 160, w5, s0, s1, s2, s3, s4, s5, s6, s7);
    acc_col(xs, lane + 192, w6, s0, s1, s2, s3, s4, s5, s6, s7);
    acc_col(xs, lane + 224, w7, s0, s1, s2, s3, s4, s5, s6, s7);

    #pragma unroll
    for (int off = 16; off; off >>= 1) {
        s0 += __shfl_xor_sync(0xffffffffu, s0, off);
        s1 += __shfl_xor_sync(0xffffffffu, s1, off);
        s2 += __shfl_xor_sync(0xffffffffu, s2, off);
        s3 += __shfl_xor_sync(0xffffffffu, s3, off);
        s4 += __shfl_xor_sync(0xffffffffu, s4, off);
        s5 += __shfl_xor_sync(0xffffffffu, s5, off);
        s6 += __shfl_xor_sync(0xffffffffu, s6, off);
        s7 += __shfl_xor_sync(0xffffffffu, s7, off);
    }

    if (lane == 0) {
        out[0 * DD + e] = s0 + bias;
        out[1 * DD + e] = s1 + bias;
        out[2 * DD + e] = s2 + bias;
        out[3 * DD + e] = s3 + bias;
        out[4 * DD + e] = s4 + bias;
        out[5 * DD + e] = s5 + bias;
        out[6 * DD + e] = s6 + bias;
        out[7 * DD + e] = s7 + bias;
    }

    // ---- Counter reset for graph replay (after all CTAs passed spin) ---
    __syncthreads();
    if (t == 0) {
        int o = atomicAdd(&g_done, 1);
        if (o == GEMV_CTAS - 1) {
            atomicExch(&g_cnt, 0);
            atomicExch(&g_done, 0);
        }
    }
}

// ---------------------------------------------------------------------------
// kernel_launch — graph-capturable, allocation-free, deterministic.
// Input order (metadata): 0=x, 1=Wq, 2=bq, 3=Wk, 4=bk, 5=Wv, 6=bv
// ---------------------------------------------------------------------------
extern "C" void kernel_launch(void* const* d_in, const int* in_sizes, int n_in,
                              void* d_out, int out_size) {
    (void)in_sizes; (void)n_in; (void)out_size;
    const float* x  = (const float*)d_in[0];
    const float* Wv = (const float*)d_in[5];
    const float* bv = (const float*)d_in[6];
    float* out = (float*)d_out;

    colsum_kernel<<<dim3(CHUNKS, BB), 256>>>(x);
    gemv_fused_kernel<<<GEMV_CTAS, 256>>>(Wv, bv, out);
}